// round 14
// baseline (speedup 1.0000x reference)
#include <cuda_runtime.h>
#include <cuda_bf16.h>
#include <cuda_fp16.h>
#include <cstdint>

#define Bn 4
#define Tn 2048
#define Cn 1024
#define Hn 16
#define Mn (Bn * Tn)

// ---------------- scratch (__device__ globals, no runtime alloc) ------------
__device__ __align__(16) __half g_xhi[(size_t)Mn * Cn];
__device__ __align__(16) __half g_xlo[(size_t)Mn * Cn];
__device__ __align__(16) __half g_wqkv16[(size_t)Cn * 3 * Cn];
__device__ __align__(16) __half g_wproj16[(size_t)Cn * Cn];
__device__ __align__(16) __half g_qkvh[(size_t)Mn * 3 * Cn];
__device__ __align__(16) __half g_qkvl[(size_t)Mn * 3 * Cn];
__device__ __align__(16) __half g_atthi[(size_t)Mn * Cn];
__device__ __align__(16) __half g_attlo[(size_t)Mn * Cn];

// ---------------- helpers ----------------------------------------------------
__device__ __forceinline__ uint32_t pk_f16x2(float lo, float hi) {
    __half2 h = __floats2half2_rn(lo, hi);
    return *(uint32_t*)&h;
}
__device__ __forceinline__ float f16low(uint32_t u)  { return __low2float(*(__half2*)&u); }
__device__ __forceinline__ float f16high(uint32_t u) { return __high2float(*(__half2*)&u); }

__device__ __forceinline__ void ldsm4(uint32_t& r0, uint32_t& r1, uint32_t& r2,
                                      uint32_t& r3, uint32_t a) {
    asm volatile("ldmatrix.sync.aligned.m8n8.x4.shared.b16 {%0,%1,%2,%3}, [%4];"
                 : "=r"(r0), "=r"(r1), "=r"(r2), "=r"(r3) : "r"(a));
}
__device__ __forceinline__ void ldsm4t(uint32_t& r0, uint32_t& r1, uint32_t& r2,
                                       uint32_t& r3, uint32_t a) {
    asm volatile("ldmatrix.sync.aligned.m8n8.x4.trans.shared.b16 {%0,%1,%2,%3}, [%4];"
                 : "=r"(r0), "=r"(r1), "=r"(r2), "=r"(r3) : "r"(a));
}
__device__ __forceinline__ void hmma16(float d[4], const uint32_t a[4], const uint32_t b[2]) {
    asm volatile(
        "mma.sync.aligned.m16n8k16.row.col.f32.f16.f16.f32 "
        "{%0,%1,%2,%3}, {%4,%5,%6,%7}, {%8,%9}, {%0,%1,%2,%3};"
        : "+f"(d[0]), "+f"(d[1]), "+f"(d[2]), "+f"(d[3])
        : "r"(a[0]), "r"(a[1]), "r"(a[2]), "r"(a[3]), "r"(b[0]), "r"(b[1]));
}
__device__ __forceinline__ void cpa16(uint32_t s, const void* g) {
    asm volatile("cp.async.cg.shared.global [%0], [%1], 16;" :: "r"(s), "l"(g) : "memory");
}

// ---------------- pack fp32 -> hi/lo fp16 (X, exact 2-term split) -------------
__global__ __launch_bounds__(256)
void pack_hilo16_kernel(const float4* __restrict__ in, uint2* __restrict__ ohi,
                        uint2* __restrict__ olo, int n4)
{
    int i = blockIdx.x * 256 + threadIdx.x;
    if (i >= n4) return;
    float4 v = in[i];
    uint32_t h0 = pk_f16x2(v.x, v.y);
    uint32_t h1 = pk_f16x2(v.z, v.w);
    ohi[i] = make_uint2(h0, h1);
    olo[i] = make_uint2(pk_f16x2(v.x - f16low(h0), v.y - f16high(h0)),
                        pk_f16x2(v.z - f16low(h1), v.w - f16high(h1)));
}

// ---------------- pack fp32 -> single fp16 (weights) ---------------------------
__global__ __launch_bounds__(256)
void pack16_kernel(const float4* __restrict__ in, uint2* __restrict__ o, int n4)
{
    int i = blockIdx.x * 256 + threadIdx.x;
    if (i >= n4) return;
    float4 v = in[i];
    o[i] = make_uint2(pk_f16x2(v.x, v.y), pk_f16x2(v.z, v.w));
}

// ---------------- fp16 2-term HMMA GEMM, 4 warps x 64x64 warp tiles ------------
// C[M,N] = (Ahi+Alo)[M,K] @ B16[K,N] + bias   (B single fp16)
// 3-stage cp.async ring, ONE __syncthreads per k-chunk.
// OUT_MODE 0: fp32 out. OUT_MODE 1: fp16 hi/lo split out.
#define ABUF 8192
#define BBUF 8704
#define STAGE (2 * ABUF + BBUF)          // 25088
#define GEMM_SMEM (3 * STAGE)            // 75264

template <int OUT_MODE>
__global__ __launch_bounds__(128, 2)
void gemm_f16x2(const uint4* __restrict__ Ahi, const uint4* __restrict__ Alo,
                const uint4* __restrict__ B16,
                const float* __restrict__ bias, float* __restrict__ Cm,
                __half* __restrict__ Chi, __half* __restrict__ Clo,
                int M, int N, int K)
{
    extern __shared__ __align__(1024) char dsm[];
    const int tid  = threadIdx.x;
    const int lane = tid & 31;
    const int warp = tid >> 5;
    const int wm   = warp >> 1;
    const int wn   = warp & 1;
    const int row0 = blockIdx.y * 128;
    const int col0 = blockIdx.x * 128;
    const uint32_t sb0 = (uint32_t)__cvta_generic_to_shared(dsm);

    const int NT = K >> 5;
    const int Kv = K >> 3;
    const int Nv = N >> 3;

    const int ar = tid >> 2;
    const int ag = tid & 3;
    const int bkr = tid >> 4;
    const int bc  = tid & 15;

    const int L  = lane;
    const int fr = (L & 7) + ((L >> 3) & 1) * 8;
    const int fa = ((L & 7) & 6) << 1;
    const uint32_t aoff = (uint32_t)(((wm * 64 + fr) * 16 + ((4 * (L >> 4)) ^ fa)) * 4);
    const uint32_t boff = (uint32_t)(fr * 272 + (wn * 64 + (L >> 4) * 8) * 2);

    auto load_chunk = [&](int ck) {
        uint32_t sb = sb0 + (uint32_t)((ck % 3) * STAGE);
#pragma unroll
        for (int i = 0; i < 4; i++) {
            int m = ar + i * 32;
            int f = (m & 6) << 1;
            uint32_t so = (uint32_t)((m * 16 + ((4 * ag) ^ f)) * 4);
            size_t ga = (size_t)(row0 + m) * Kv + ck * 4 + ag;
            cpa16(sb + so,        Ahi + ga);
            cpa16(sb + ABUF + so, Alo + ga);
        }
#pragma unroll
        for (int i = 0; i < 4; i++) {
            int kr = bkr + i * 8;
            uint32_t so = (uint32_t)(kr * 272 + bc * 16);
            size_t gb = (size_t)(ck * 32 + kr) * Nv + (col0 >> 3) + bc;
            cpa16(sb + 2 * ABUF + so, B16 + gb);
        }
        asm volatile("cp.async.commit_group;" ::: "memory");
    };

    float acc[4][8][4];
#pragma unroll
    for (int mi = 0; mi < 4; mi++)
#pragma unroll
        for (int na = 0; na < 8; na++)
#pragma unroll
            for (int r = 0; r < 4; r++) acc[mi][na][r] = 0.0f;

    load_chunk(0);
    load_chunk(1);

    for (int kt = 0; kt < NT; kt++) {
        if (kt + 1 < NT) asm volatile("cp.async.wait_group 1;" ::: "memory");
        else             asm volatile("cp.async.wait_group 0;" ::: "memory");
        __syncthreads();   // chunk kt visible; buffer (kt+2)%3 readers all done

        if (kt + 2 < NT) load_chunk(kt + 2);

        uint32_t sa  = sb0 + (uint32_t)((kt % 3) * STAGE);
        uint32_t sbB = sa + 2 * ABUF;

#pragma unroll
        for (int ks = 0; ks < 2; ks++) {
            const uint32_t ax = (uint32_t)(ks * 32);
            uint32_t a_hi[4][4], a_lo[4][4];
#pragma unroll
            for (int mi = 0; mi < 4; mi++) {
                uint32_t ad = (sa + aoff + (uint32_t)(mi * 1024)) ^ ax;
                ldsm4(a_hi[mi][0], a_hi[mi][1], a_hi[mi][2], a_hi[mi][3], ad);
                ldsm4(a_lo[mi][0], a_lo[mi][1], a_lo[mi][2], a_lo[mi][3], ad + ABUF);
            }
#pragma unroll
            for (int nh = 0; nh < 2; nh++) {
                uint32_t bd = sbB + boff + (uint32_t)(nh * 64 + ks * 4352);
                uint32_t bfr[4][2];
                ldsm4t(bfr[0][0], bfr[0][1], bfr[1][0], bfr[1][1], bd);
                ldsm4t(bfr[2][0], bfr[2][1], bfr[3][0], bfr[3][1], bd + 32);
#pragma unroll
                for (int mi = 0; mi < 4; mi++)
#pragma unroll
                    for (int ni = 0; ni < 4; ni++)
                        hmma16(acc[mi][nh * 4 + ni], a_hi[mi], bfr[ni]);
#pragma unroll
                for (int mi = 0; mi < 4; mi++)
#pragma unroll
                    for (int ni = 0; ni < 4; ni++)
                        hmma16(acc[mi][nh * 4 + ni], a_lo[mi], bfr[ni]);
            }
        }
    }

    // ---- epilogue ----
    const int g = lane >> 2, qd = lane & 3;
#pragma unroll
    for (int mi = 0; mi < 4; mi++) {
        int row = row0 + wm * 64 + mi * 16 + g;
#pragma unroll
        for (int na = 0; na < 8; na++) {
            int col = col0 + wn * 64 + na * 8 + 2 * qd;
            float2 bv = *(const float2*)&bias[col];
            float v0 = acc[mi][na][0] + bv.x, v1 = acc[mi][na][1] + bv.y;
            float v2 = acc[mi][na][2] + bv.x, v3 = acc[mi][na][3] + bv.y;
            if (OUT_MODE == 0) {
                *(float2*)&Cm[(size_t)row * N + col]       = make_float2(v0, v1);
                *(float2*)&Cm[(size_t)(row + 8) * N + col] = make_float2(v2, v3);
            } else {
                uint32_t hh = pk_f16x2(v0, v1);
                size_t i0 = ((size_t)row * N + col) >> 1;
                ((uint32_t*)Chi)[i0] = hh;
                ((uint32_t*)Clo)[i0] = pk_f16x2(v0 - f16low(hh), v1 - f16high(hh));
                hh = pk_f16x2(v2, v3);
                size_t i1 = ((size_t)(row + 8) * N + col) >> 1;
                ((uint32_t*)Chi)[i1] = hh;
                ((uint32_t*)Clo)[i1] = pk_f16x2(v2 - f16low(hh), v3 - f16high(hh));
            }
        }
    }
}

// ---------------- fp16 2-term flash attention (causal) ------------------------
// 64 q-rows, 4 warps. KV tile t+1 prefetched into REGISTERS during compute(t):
// only STS+sync latency exposed per tile.
__global__ __launch_bounds__(128)
void attn_mma_kernel(const __half* __restrict__ qh,
                     const __half* __restrict__ ql,
                     __half* __restrict__ atthi,
                     __half* __restrict__ attlo)
{
    __shared__ __align__(16) __half sKh[64 * 72];
    __shared__ __align__(16) __half sVh[64 * 72];

    const int tid  = threadIdx.x;
    const int lane = tid & 31;
    const int warp = tid >> 5;
    const int qt   = (int)(gridDim.x - 1) - (int)blockIdx.x;  // heavy tiles first
    const int bh   = blockIdx.y;
    const int b    = bh >> 4, h = bh & 15;
    const int q0   = qt * 64;
    const int m0w  = warp * 16;
    const int g    = lane >> 2, qd = lane & 3;
    const size_t rowbase = (size_t)b * Tn;
    const int hcol = h * 64;

    const int fr = (lane & 7) + ((lane >> 3) & 1) * 8;
    const int hb = (lane >> 4) * 16;
    const int sr = tid >> 3;          // staging row (per-thread, fixed)
    const int sc = tid & 7;           // staging col

    uint32_t sKh_b = (uint32_t)__cvta_generic_to_shared(sKh);
    uint32_t sVh_b = (uint32_t)__cvta_generic_to_shared(sVh);

    // KV register prefetch buffers
    uint4 kreg[4], vreg[4];
    auto ldg_tile = [&](int t) {
        const int kv0 = t * 64;
#pragma unroll
        for (int it = 0; it < 4; it++) {
            size_t grow = (rowbase + kv0 + sr + it * 16) * (3 * Cn) + hcol;
            kreg[it] = *((const uint4*)(qh + grow + Cn) + sc);
            vreg[it] = *((const uint4*)(qh + grow + 2 * Cn) + sc);
        }
    };

    // issue tile-0 KV loads first (overlap with Q staging)
    ldg_tile(0);

    // ---- stage Q: hi -> sKh, lo -> sVh; fragments into registers ----
#pragma unroll
    for (int it = 0; it < 4; it++) {
        size_t grow = (rowbase + q0 + sr + it * 16) * (3 * Cn) + hcol;
        ((uint4*)sKh)[(sr + it * 16) * 9 + sc] = *((const uint4*)(qh + grow) + sc);
        ((uint4*)sVh)[(sr + it * 16) * 9 + sc] = *((const uint4*)(ql + grow) + sc);
    }
    __syncthreads();

    uint32_t qhi[4][4], qlo[4][4];
#pragma unroll
    for (int j = 0; j < 4; j++) {
        uint32_t ad = (uint32_t)((m0w + fr) * 144 + j * 32 + hb);
        ldsm4(qhi[j][0], qhi[j][1], qhi[j][2], qhi[j][3], sKh_b + ad);
        ldsm4(qlo[j][0], qlo[j][1], qlo[j][2], qlo[j][3], sVh_b + ad);
    }

    float o[8][4];
#pragma unroll
    for (int nt = 0; nt < 8; nt++)
#pragma unroll
        for (int r = 0; r < 4; r++) o[nt][r] = 0.0f;
    float m0r = -1e30f, m1r = -1e30f, l0 = 0.0f, l1 = 0.0f;

    const float scale = 0.125f;
    const int rl0 = m0w + g, rl1 = rl0 + 8;

    for (int t = 0; t <= qt; t++) {
        __syncthreads();   // everyone done reading smem (Q frags at t=0, KV t-1 after)
#pragma unroll
        for (int it = 0; it < 4; it++) {
            ((uint4*)sKh)[(sr + it * 16) * 9 + sc] = kreg[it];
            ((uint4*)sVh)[(sr + it * 16) * 9 + sc] = vreg[it];
        }
        __syncthreads();

        if (t < qt) ldg_tile(t + 1);   // prefetch under compute

        // ---- S = Q K^T (2-term fp16) ----
        float s[8][4];
#pragma unroll
        for (int nt = 0; nt < 8; nt++)
#pragma unroll
            for (int r = 0; r < 4; r++) s[nt][r] = 0.0f;

#pragma unroll
        for (int p = 0; p < 4; p++) {
#pragma unroll
            for (int j = 0; j < 4; j++) {
                uint32_t kh0, kh1, kh2, kh3;
                uint32_t ad = (uint32_t)((p * 16 + fr) * 144 + j * 32 + hb);
                ldsm4(kh0, kh1, kh2, kh3, sKh_b + ad);
                uint32_t b0h[2] = {kh0, kh2}, b1h[2] = {kh1, kh3};
                hmma16(s[2 * p],     qhi[j], b0h);
                hmma16(s[2 * p],     qlo[j], b0h);
                hmma16(s[2 * p + 1], qhi[j], b1h);
                hmma16(s[2 * p + 1], qlo[j], b1h);
            }
        }

        // ---- scale + causal mask (diagonal tile only) ----
#pragma unroll
        for (int nt = 0; nt < 8; nt++) {
            s[nt][0] *= scale; s[nt][1] *= scale;
            s[nt][2] *= scale; s[nt][3] *= scale;
        }
        if (t == qt) {
#pragma unroll
            for (int nt = 0; nt < 8; nt++) {
                int c0 = nt * 8 + 2 * qd;
                if (c0     > rl0) s[nt][0] = -1e30f;
                if (c0 + 1 > rl0) s[nt][1] = -1e30f;
                if (c0     > rl1) s[nt][2] = -1e30f;
                if (c0 + 1 > rl1) s[nt][3] = -1e30f;
            }
        }

        // ---- online softmax (rows g and g+8) ----
        float mx0 = -1e30f, mx1 = -1e30f;
#pragma unroll
        for (int nt = 0; nt < 8; nt++) {
            mx0 = fmaxf(mx0, fmaxf(s[nt][0], s[nt][1]));
            mx1 = fmaxf(mx1, fmaxf(s[nt][2], s[nt][3]));
        }
        mx0 = fmaxf(mx0, __shfl_xor_sync(0xffffffffu, mx0, 1));
        mx0 = fmaxf(mx0, __shfl_xor_sync(0xffffffffu, mx0, 2));
        mx1 = fmaxf(mx1, __shfl_xor_sync(0xffffffffu, mx1, 1));
        mx1 = fmaxf(mx1, __shfl_xor_sync(0xffffffffu, mx1, 2));
        float mn0 = fmaxf(m0r, mx0), mn1 = fmaxf(m1r, mx1);
        float cf0 = __expf(m0r - mn0), cf1 = __expf(m1r - mn1);
        m0r = mn0; m1r = mn1;
        float sum0 = 0.0f, sum1 = 0.0f;
#pragma unroll
        for (int nt = 0; nt < 8; nt++) {
            s[nt][0] = __expf(s[nt][0] - mn0); sum0 += s[nt][0];
            s[nt][1] = __expf(s[nt][1] - mn0); sum0 += s[nt][1];
            s[nt][2] = __expf(s[nt][2] - mn1); sum1 += s[nt][2];
            s[nt][3] = __expf(s[nt][3] - mn1); sum1 += s[nt][3];
        }
        sum0 += __shfl_xor_sync(0xffffffffu, sum0, 1);
        sum0 += __shfl_xor_sync(0xffffffffu, sum0, 2);
        sum1 += __shfl_xor_sync(0xffffffffu, sum1, 1);
        sum1 += __shfl_xor_sync(0xffffffffu, sum1, 2);
        l0 = l0 * cf0 + sum0;
        l1 = l1 * cf1 + sum1;
#pragma unroll
        for (int nt = 0; nt < 8; nt++) {
            o[nt][0] *= cf0; o[nt][1] *= cf0;
            o[nt][2] *= cf1; o[nt][3] *= cf1;
        }

        // ---- O += P V (2-term fp16: P split exact, V single) ----
#pragma unroll
        for (int j = 0; j < 4; j++) {
            uint32_t phi[4], plo[4];
            uint32_t hh;
            hh = pk_f16x2(s[2 * j][0], s[2 * j][1]);
            phi[0] = hh;
            plo[0] = pk_f16x2(s[2 * j][0] - f16low(hh), s[2 * j][1] - f16high(hh));
            hh = pk_f16x2(s[2 * j][2], s[2 * j][3]);
            phi[1] = hh;
            plo[1] = pk_f16x2(s[2 * j][2] - f16low(hh), s[2 * j][3] - f16high(hh));
            hh = pk_f16x2(s[2 * j + 1][0], s[2 * j + 1][1]);
            phi[2] = hh;
            plo[2] = pk_f16x2(s[2 * j + 1][0] - f16low(hh), s[2 * j + 1][1] - f16high(hh));
            hh = pk_f16x2(s[2 * j + 1][2], s[2 * j + 1][3]);
            phi[3] = hh;
            plo[3] = pk_f16x2(s[2 * j + 1][2] - f16low(hh), s[2 * j + 1][3] - f16high(hh));

#pragma unroll
            for (int p = 0; p < 4; p++) {
                uint32_t v0, v1, v2, v3;
                uint32_t ad = (uint32_t)((j * 16 + fr) * 144 + p * 32 + hb);
                ldsm4t(v0, v1, v2, v3, sVh_b + ad);
                uint32_t bh0[2] = {v0, v1}, bh1[2] = {v2, v3};
                hmma16(o[2 * p],     phi, bh0);
                hmma16(o[2 * p],     plo, bh0);
                hmma16(o[2 * p + 1], phi, bh1);
                hmma16(o[2 * p + 1], plo, bh1);
            }
        }
    }

    // ---- epilogue: normalize, split hi/lo fp16, store ----
    float inv0 = 1.0f / l0, inv1 = 1.0f / l1;
    size_t orow0 = (rowbase + q0 + m0w + g) * Cn + hcol;
    size_t orow1 = orow0 + (size_t)8 * Cn;
#pragma unroll
    for (int nt = 0; nt < 8; nt++) {
        int c = nt * 8 + 2 * qd;
        float v0 = o[nt][0] * inv0, v1 = o[nt][1] * inv0;
        uint32_t hh = pk_f16x2(v0, v1);
        ((uint32_t*)atthi)[(orow0 + c) >> 1] = hh;
        ((uint32_t*)attlo)[(orow0 + c) >> 1] =
            pk_f16x2(v0 - f16low(hh), v1 - f16high(hh));
        v0 = o[nt][2] * inv1; v1 = o[nt][3] * inv1;
        hh = pk_f16x2(v0, v1);
        ((uint32_t*)atthi)[(orow1 + c) >> 1] = hh;
        ((uint32_t*)attlo)[(orow1 + c) >> 1] =
            pk_f16x2(v0 - f16low(hh), v1 - f16high(hh));
    }
}

// ---------------------------------------------------------------------------
extern "C" void kernel_launch(void* const* d_in, const int* in_sizes, int n_in,
                              void* d_out, int out_size)
{
    const float* x     = (const float*)d_in[0];
    const float* Wqkv  = (const float*)d_in[1];
    const float* bqkv  = (const float*)d_in[2];
    const float* Wproj = (const float*)d_in[3];
    const float* bproj = (const float*)d_in[4];
    float* out = (float*)d_out;

    __half *xhi, *xlo, *wq16, *wp16, *qkvh, *qkvl, *ahi, *alo;
    cudaGetSymbolAddress((void**)&xhi, g_xhi);
    cudaGetSymbolAddress((void**)&xlo, g_xlo);
    cudaGetSymbolAddress((void**)&wq16, g_wqkv16);
    cudaGetSymbolAddress((void**)&wp16, g_wproj16);
    cudaGetSymbolAddress((void**)&qkvh, g_qkvh);
    cudaGetSymbolAddress((void**)&qkvl, g_qkvl);
    cudaGetSymbolAddress((void**)&ahi, g_atthi);
    cudaGetSymbolAddress((void**)&alo, g_attlo);

    cudaFuncSetAttribute(gemm_f16x2<0>, cudaFuncAttributeMaxDynamicSharedMemorySize, GEMM_SMEM);
    cudaFuncSetAttribute(gemm_f16x2<1>, cudaFuncAttributeMaxDynamicSharedMemorySize, GEMM_SMEM);

    int nx = Mn * Cn / 4, nwq = Cn * 3 * Cn / 4, nwp = Cn * Cn / 4;
    pack_hilo16_kernel<<<(nx + 255) / 256, 256>>>((const float4*)x, (uint2*)xhi, (uint2*)xlo, nx);
    pack16_kernel<<<(nwq + 255) / 256, 256>>>((const float4*)Wqkv, (uint2*)wq16, nwq);
    pack16_kernel<<<(nwp + 255) / 256, 256>>>((const float4*)Wproj, (uint2*)wp16, nwp);

    // 1) QKV = X @ W_qkv + b  -> fp16 hi/lo
    gemm_f16x2<1><<<dim3(3 * Cn / 128, Mn / 128), 128, GEMM_SMEM>>>(
        (const uint4*)xhi, (const uint4*)xlo, (const uint4*)wq16,
        bqkv, nullptr, qkvh, qkvl, Mn, 3 * Cn, Cn);

    // 2) causal flash attention (fp16 2-term); emits fp16 hi/lo att
    attn_mma_kernel<<<dim3(Tn / 64, Bn * Hn), 128>>>(qkvh, qkvl, ahi, alo);

    // 3) out = att @ W_proj + b  (fp32 out)
    gemm_f16x2<0><<<dim3(Cn / 128, Mn / 128), 128, GEMM_SMEM>>>(
        (const uint4*)ahi, (const uint4*)alo, (const uint4*)wp16,
        bproj, out, nullptr, nullptr, Mn, Cn, Cn);
}

// round 15
// speedup vs baseline: 1.0265x; 1.0265x over previous
#include <cuda_runtime.h>
#include <cuda_bf16.h>
#include <cuda_fp16.h>
#include <cstdint>

#define Bn 4
#define Tn 2048
#define Cn 1024
#define Hn 16
#define Mn (Bn * Tn)

// ---------------- scratch (__device__ globals, no runtime alloc) ------------
__device__ __align__(16) __half g_xhi[(size_t)Mn * Cn];
__device__ __align__(16) __half g_xlo[(size_t)Mn * Cn];
__device__ __align__(16) __half g_wqkv16[(size_t)Cn * 3 * Cn];
__device__ __align__(16) __half g_wproj16[(size_t)Cn * Cn];
__device__ __align__(16) __half g_qkvh[(size_t)Mn * 3 * Cn];
__device__ __align__(16) __half g_qkvl[(size_t)Mn * 3 * Cn];
__device__ __align__(16) __half g_atthi[(size_t)Mn * Cn];
__device__ __align__(16) __half g_attlo[(size_t)Mn * Cn];

// ---------------- helpers ----------------------------------------------------
__device__ __forceinline__ uint32_t pk_f16x2(float lo, float hi) {
    __half2 h = __floats2half2_rn(lo, hi);
    return *(uint32_t*)&h;
}
__device__ __forceinline__ float f16low(uint32_t u)  { return __low2float(*(__half2*)&u); }
__device__ __forceinline__ float f16high(uint32_t u) { return __high2float(*(__half2*)&u); }

__device__ __forceinline__ void ldsm4(uint32_t& r0, uint32_t& r1, uint32_t& r2,
                                      uint32_t& r3, uint32_t a) {
    asm volatile("ldmatrix.sync.aligned.m8n8.x4.shared.b16 {%0,%1,%2,%3}, [%4];"
                 : "=r"(r0), "=r"(r1), "=r"(r2), "=r"(r3) : "r"(a));
}
__device__ __forceinline__ void ldsm4t(uint32_t& r0, uint32_t& r1, uint32_t& r2,
                                       uint32_t& r3, uint32_t a) {
    asm volatile("ldmatrix.sync.aligned.m8n8.x4.trans.shared.b16 {%0,%1,%2,%3}, [%4];"
                 : "=r"(r0), "=r"(r1), "=r"(r2), "=r"(r3) : "r"(a));
}
__device__ __forceinline__ void hmma16(float d[4], const uint32_t a[4], const uint32_t b[2]) {
    asm volatile(
        "mma.sync.aligned.m16n8k16.row.col.f32.f16.f16.f32 "
        "{%0,%1,%2,%3}, {%4,%5,%6,%7}, {%8,%9}, {%0,%1,%2,%3};"
        : "+f"(d[0]), "+f"(d[1]), "+f"(d[2]), "+f"(d[3])
        : "r"(a[0]), "r"(a[1]), "r"(a[2]), "r"(a[3]), "r"(b[0]), "r"(b[1]));
}
__device__ __forceinline__ void cpa16(uint32_t s, const void* g) {
    asm volatile("cp.async.cg.shared.global [%0], [%1], 16;" :: "r"(s), "l"(g) : "memory");
}

// ---------------- pack fp32 -> hi/lo fp16 (X, exact 2-term split) -------------
__global__ __launch_bounds__(256)
void pack_hilo16_kernel(const float4* __restrict__ in, uint2* __restrict__ ohi,
                        uint2* __restrict__ olo, int n4)
{
    int i = blockIdx.x * 256 + threadIdx.x;
    if (i >= n4) return;
    float4 v = in[i];
    uint32_t h0 = pk_f16x2(v.x, v.y);
    uint32_t h1 = pk_f16x2(v.z, v.w);
    ohi[i] = make_uint2(h0, h1);
    olo[i] = make_uint2(pk_f16x2(v.x - f16low(h0), v.y - f16high(h0)),
                        pk_f16x2(v.z - f16low(h1), v.w - f16high(h1)));
}

// ---------------- pack fp32 -> single fp16 (weights) ---------------------------
__global__ __launch_bounds__(256)
void pack16_kernel(const float4* __restrict__ in, uint2* __restrict__ o, int n4)
{
    int i = blockIdx.x * 256 + threadIdx.x;
    if (i >= n4) return;
    float4 v = in[i];
    o[i] = make_uint2(pk_f16x2(v.x, v.y), pk_f16x2(v.z, v.w));
}

// ---------------- fp16 2-term HMMA GEMM, 4 warps x 64x64 warp tiles ------------
// C[M,N] = (Ahi+Alo)[M,K] @ B16[K,N] + bias   (B single fp16)
// 4-stage cp.async ring, prefetch depth 2, loads PRE-sync, ONE sync/iter:
// write target (kt+2)%4 was read at kt-2, whose readers passed sync(kt-1).
// OUT_MODE 0: fp32 out. OUT_MODE 1: fp16 hi/lo split out.
#define ABUF 8192
#define BBUF 8704
#define STAGE (2 * ABUF + BBUF)          // 25088
#define GEMM_SMEM (4 * STAGE)            // 100352

template <int OUT_MODE>
__global__ __launch_bounds__(128, 2)
void gemm_f16x2(const uint4* __restrict__ Ahi, const uint4* __restrict__ Alo,
                const uint4* __restrict__ B16,
                const float* __restrict__ bias, float* __restrict__ Cm,
                __half* __restrict__ Chi, __half* __restrict__ Clo,
                int M, int N, int K)
{
    extern __shared__ __align__(1024) char dsm[];
    const int tid  = threadIdx.x;
    const int lane = tid & 31;
    const int warp = tid >> 5;
    const int wm   = warp >> 1;
    const int wn   = warp & 1;
    const int row0 = blockIdx.y * 128;
    const int col0 = blockIdx.x * 128;
    const uint32_t sb0 = (uint32_t)__cvta_generic_to_shared(dsm);

    const int NT = K >> 5;
    const int Kv = K >> 3;
    const int Nv = N >> 3;

    const int ar = tid >> 2;
    const int ag = tid & 3;
    const int bkr = tid >> 4;
    const int bc  = tid & 15;

    const int L  = lane;
    const int fr = (L & 7) + ((L >> 3) & 1) * 8;
    const int fa = ((L & 7) & 6) << 1;
    const uint32_t aoff = (uint32_t)(((wm * 64 + fr) * 16 + ((4 * (L >> 4)) ^ fa)) * 4);
    const uint32_t boff = (uint32_t)(fr * 272 + (wn * 64 + (L >> 4) * 8) * 2);

    auto load_chunk = [&](int ck) {
        uint32_t sb = sb0 + (uint32_t)((ck & 3) * STAGE);
#pragma unroll
        for (int i = 0; i < 4; i++) {
            int m = ar + i * 32;
            int f = (m & 6) << 1;
            uint32_t so = (uint32_t)((m * 16 + ((4 * ag) ^ f)) * 4);
            size_t ga = (size_t)(row0 + m) * Kv + ck * 4 + ag;
            cpa16(sb + so,        Ahi + ga);
            cpa16(sb + ABUF + so, Alo + ga);
        }
#pragma unroll
        for (int i = 0; i < 4; i++) {
            int kr = bkr + i * 8;
            uint32_t so = (uint32_t)(kr * 272 + bc * 16);
            size_t gb = (size_t)(ck * 32 + kr) * Nv + (col0 >> 3) + bc;
            cpa16(sb + 2 * ABUF + so, B16 + gb);
        }
        asm volatile("cp.async.commit_group;" ::: "memory");
    };

    float acc[4][8][4];
#pragma unroll
    for (int mi = 0; mi < 4; mi++)
#pragma unroll
        for (int na = 0; na < 8; na++)
#pragma unroll
            for (int r = 0; r < 4; r++) acc[mi][na][r] = 0.0f;

    load_chunk(0);
    load_chunk(1);

    for (int kt = 0; kt < NT; kt++) {
        // prefetch chunk kt+2 into buffer (kt+2)&3 = (kt-2)&3 — safe pre-sync
        if (kt + 2 < NT) {
            load_chunk(kt + 2);
            asm volatile("cp.async.wait_group 2;" ::: "memory");
        } else if (kt + 1 < NT) {
            asm volatile("cp.async.wait_group 1;" ::: "memory");
        } else {
            asm volatile("cp.async.wait_group 0;" ::: "memory");
        }
        __syncthreads();   // chunk kt visible; also closes reader window of kt-2

        uint32_t sa  = sb0 + (uint32_t)((kt & 3) * STAGE);
        uint32_t sbB = sa + 2 * ABUF;

#pragma unroll
        for (int ks = 0; ks < 2; ks++) {
            const uint32_t ax = (uint32_t)(ks * 32);
            uint32_t a_hi[4][4], a_lo[4][4];
#pragma unroll
            for (int mi = 0; mi < 4; mi++) {
                uint32_t ad = (sa + aoff + (uint32_t)(mi * 1024)) ^ ax;
                ldsm4(a_hi[mi][0], a_hi[mi][1], a_hi[mi][2], a_hi[mi][3], ad);
                ldsm4(a_lo[mi][0], a_lo[mi][1], a_lo[mi][2], a_lo[mi][3], ad + ABUF);
            }
#pragma unroll
            for (int nh = 0; nh < 2; nh++) {
                uint32_t bd = sbB + boff + (uint32_t)(nh * 64 + ks * 4352);
                uint32_t bfr[4][2];
                ldsm4t(bfr[0][0], bfr[0][1], bfr[1][0], bfr[1][1], bd);
                ldsm4t(bfr[2][0], bfr[2][1], bfr[3][0], bfr[3][1], bd + 32);
#pragma unroll
                for (int mi = 0; mi < 4; mi++)
#pragma unroll
                    for (int ni = 0; ni < 4; ni++)
                        hmma16(acc[mi][nh * 4 + ni], a_hi[mi], bfr[ni]);
#pragma unroll
                for (int mi = 0; mi < 4; mi++)
#pragma unroll
                    for (int ni = 0; ni < 4; ni++)
                        hmma16(acc[mi][nh * 4 + ni], a_lo[mi], bfr[ni]);
            }
        }
    }

    // ---- epilogue ----
    const int g = lane >> 2, qd = lane & 3;
#pragma unroll
    for (int mi = 0; mi < 4; mi++) {
        int row = row0 + wm * 64 + mi * 16 + g;
#pragma unroll
        for (int na = 0; na < 8; na++) {
            int col = col0 + wn * 64 + na * 8 + 2 * qd;
            float2 bv = *(const float2*)&bias[col];
            float v0 = acc[mi][na][0] + bv.x, v1 = acc[mi][na][1] + bv.y;
            float v2 = acc[mi][na][2] + bv.x, v3 = acc[mi][na][3] + bv.y;
            if (OUT_MODE == 0) {
                *(float2*)&Cm[(size_t)row * N + col]       = make_float2(v0, v1);
                *(float2*)&Cm[(size_t)(row + 8) * N + col] = make_float2(v2, v3);
            } else {
                uint32_t hh = pk_f16x2(v0, v1);
                size_t i0 = ((size_t)row * N + col) >> 1;
                ((uint32_t*)Chi)[i0] = hh;
                ((uint32_t*)Clo)[i0] = pk_f16x2(v0 - f16low(hh), v1 - f16high(hh));
                hh = pk_f16x2(v2, v3);
                size_t i1 = ((size_t)(row + 8) * N + col) >> 1;
                ((uint32_t*)Chi)[i1] = hh;
                ((uint32_t*)Clo)[i1] = pk_f16x2(v2 - f16low(hh), v3 - f16high(hh));
            }
        }
    }
}

// ---------------- fp16 2-term flash attention (causal) ------------------------
// Round-13 proven kernel (64 q-rows, 4 warps), reverted exactly.
__global__ __launch_bounds__(128)
void attn_mma_kernel(const __half* __restrict__ qh,
                     const __half* __restrict__ ql,
                     __half* __restrict__ atthi,
                     __half* __restrict__ attlo)
{
    __shared__ __align__(16) __half sKh[64 * 72];
    __shared__ __align__(16) __half sVh[64 * 72];

    const int tid  = threadIdx.x;
    const int lane = tid & 31;
    const int warp = tid >> 5;
    const int qt   = (int)(gridDim.x - 1) - (int)blockIdx.x;  // heavy tiles first
    const int bh   = blockIdx.y;
    const int b    = bh >> 4, h = bh & 15;
    const int q0   = qt * 64;
    const int m0w  = warp * 16;
    const int g    = lane >> 2, qd = lane & 3;
    const size_t rowbase = (size_t)b * Tn;
    const int hcol = h * 64;

    const int fr = (lane & 7) + ((lane >> 3) & 1) * 8;
    const int hb = (lane >> 4) * 16;

    uint32_t sKh_b = (uint32_t)__cvta_generic_to_shared(sKh);
    uint32_t sVh_b = (uint32_t)__cvta_generic_to_shared(sVh);

    // ---- stage Q: hi -> sKh, lo -> sVh; fragments into registers ----
#pragma unroll
    for (int it = 0; it < 4; it++) {
        int idx = tid + it * 128;
        int r = idx >> 3, c = idx & 7;
        size_t grow = (rowbase + q0 + r) * (3 * Cn) + hcol;
        ((uint4*)sKh)[r * 9 + c] = *((const uint4*)(qh + grow) + c);
        ((uint4*)sVh)[r * 9 + c] = *((const uint4*)(ql + grow) + c);
    }
    __syncthreads();

    uint32_t qhi[4][4], qlo[4][4];
#pragma unroll
    for (int j = 0; j < 4; j++) {
        uint32_t ad = (uint32_t)((m0w + fr) * 144 + j * 32 + hb);
        ldsm4(qhi[j][0], qhi[j][1], qhi[j][2], qhi[j][3], sKh_b + ad);
        ldsm4(qlo[j][0], qlo[j][1], qlo[j][2], qlo[j][3], sVh_b + ad);
    }

    float o[8][4];
#pragma unroll
    for (int nt = 0; nt < 8; nt++)
#pragma unroll
        for (int r = 0; r < 4; r++) o[nt][r] = 0.0f;
    float m0r = -1e30f, m1r = -1e30f, l0 = 0.0f, l1 = 0.0f;

    const float scale = 0.125f;
    const int rl0 = m0w + g, rl1 = rl0 + 8;

    for (int t = 0; t <= qt; t++) {
        const int kv0 = t * 64;
        __syncthreads();
#pragma unroll
        for (int it = 0; it < 4; it++) {
            int idx = tid + it * 128;
            int r = idx >> 3, c = idx & 7;
            size_t grow = (rowbase + kv0 + r) * (3 * Cn) + hcol;
            ((uint4*)sKh)[r * 9 + c] = *((const uint4*)(qh + grow + Cn) + c);
            ((uint4*)sVh)[r * 9 + c] = *((const uint4*)(qh + grow + 2 * Cn) + c);
        }
        __syncthreads();

        // ---- S = Q K^T (2-term fp16) ----
        float s[8][4];
#pragma unroll
        for (int nt = 0; nt < 8; nt++)
#pragma unroll
            for (int r = 0; r < 4; r++) s[nt][r] = 0.0f;

#pragma unroll
        for (int p = 0; p < 4; p++) {
#pragma unroll
            for (int j = 0; j < 4; j++) {
                uint32_t kh0, kh1, kh2, kh3;
                uint32_t ad = (uint32_t)((p * 16 + fr) * 144 + j * 32 + hb);
                ldsm4(kh0, kh1, kh2, kh3, sKh_b + ad);
                uint32_t b0h[2] = {kh0, kh2}, b1h[2] = {kh1, kh3};
                hmma16(s[2 * p],     qhi[j], b0h);
                hmma16(s[2 * p],     qlo[j], b0h);
                hmma16(s[2 * p + 1], qhi[j], b1h);
                hmma16(s[2 * p + 1], qlo[j], b1h);
            }
        }

        // ---- scale + causal mask (diagonal tile only) ----
#pragma unroll
        for (int nt = 0; nt < 8; nt++) {
            s[nt][0] *= scale; s[nt][1] *= scale;
            s[nt][2] *= scale; s[nt][3] *= scale;
        }
        if (t == qt) {
#pragma unroll
            for (int nt = 0; nt < 8; nt++) {
                int c0 = nt * 8 + 2 * qd;
                if (c0     > rl0) s[nt][0] = -1e30f;
                if (c0 + 1 > rl0) s[nt][1] = -1e30f;
                if (c0     > rl1) s[nt][2] = -1e30f;
                if (c0 + 1 > rl1) s[nt][3] = -1e30f;
            }
        }

        // ---- online softmax (rows g and g+8) ----
        float mx0 = -1e30f, mx1 = -1e30f;
#pragma unroll
        for (int nt = 0; nt < 8; nt++) {
            mx0 = fmaxf(mx0, fmaxf(s[nt][0], s[nt][1]));
            mx1 = fmaxf(mx1, fmaxf(s[nt][2], s[nt][3]));
        }
        mx0 = fmaxf(mx0, __shfl_xor_sync(0xffffffffu, mx0, 1));
        mx0 = fmaxf(mx0, __shfl_xor_sync(0xffffffffu, mx0, 2));
        mx1 = fmaxf(mx1, __shfl_xor_sync(0xffffffffu, mx1, 1));
        mx1 = fmaxf(mx1, __shfl_xor_sync(0xffffffffu, mx1, 2));
        float mn0 = fmaxf(m0r, mx0), mn1 = fmaxf(m1r, mx1);
        float cf0 = __expf(m0r - mn0), cf1 = __expf(m1r - mn1);
        m0r = mn0; m1r = mn1;
        float sum0 = 0.0f, sum1 = 0.0f;
#pragma unroll
        for (int nt = 0; nt < 8; nt++) {
            s[nt][0] = __expf(s[nt][0] - mn0); sum0 += s[nt][0];
            s[nt][1] = __expf(s[nt][1] - mn0); sum0 += s[nt][1];
            s[nt][2] = __expf(s[nt][2] - mn1); sum1 += s[nt][2];
            s[nt][3] = __expf(s[nt][3] - mn1); sum1 += s[nt][3];
        }
        sum0 += __shfl_xor_sync(0xffffffffu, sum0, 1);
        sum0 += __shfl_xor_sync(0xffffffffu, sum0, 2);
        sum1 += __shfl_xor_sync(0xffffffffu, sum1, 1);
        sum1 += __shfl_xor_sync(0xffffffffu, sum1, 2);
        l0 = l0 * cf0 + sum0;
        l1 = l1 * cf1 + sum1;
#pragma unroll
        for (int nt = 0; nt < 8; nt++) {
            o[nt][0] *= cf0; o[nt][1] *= cf0;
            o[nt][2] *= cf1; o[nt][3] *= cf1;
        }

        // ---- O += P V (2-term fp16: P split exact, V single) ----
#pragma unroll
        for (int j = 0; j < 4; j++) {
            uint32_t phi[4], plo[4];
            uint32_t hh;
            hh = pk_f16x2(s[2 * j][0], s[2 * j][1]);
            phi[0] = hh;
            plo[0] = pk_f16x2(s[2 * j][0] - f16low(hh), s[2 * j][1] - f16high(hh));
            hh = pk_f16x2(s[2 * j][2], s[2 * j][3]);
            phi[1] = hh;
            plo[1] = pk_f16x2(s[2 * j][2] - f16low(hh), s[2 * j][3] - f16high(hh));
            hh = pk_f16x2(s[2 * j + 1][0], s[2 * j + 1][1]);
            phi[2] = hh;
            plo[2] = pk_f16x2(s[2 * j + 1][0] - f16low(hh), s[2 * j + 1][1] - f16high(hh));
            hh = pk_f16x2(s[2 * j + 1][2], s[2 * j + 1][3]);
            phi[3] = hh;
            plo[3] = pk_f16x2(s[2 * j + 1][2] - f16low(hh), s[2 * j + 1][3] - f16high(hh));

#pragma unroll
            for (int p = 0; p < 4; p++) {
                uint32_t v0, v1, v2, v3;
                uint32_t ad = (uint32_t)((j * 16 + fr) * 144 + p * 32 + hb);
                ldsm4t(v0, v1, v2, v3, sVh_b + ad);
                uint32_t bh0[2] = {v0, v1}, bh1[2] = {v2, v3};
                hmma16(o[2 * p],     phi, bh0);
                hmma16(o[2 * p],     plo, bh0);
                hmma16(o[2 * p + 1], phi, bh1);
                hmma16(o[2 * p + 1], plo, bh1);
            }
        }
    }

    // ---- epilogue: normalize, split hi/lo fp16, store ----
    float inv0 = 1.0f / l0, inv1 = 1.0f / l1;
    size_t orow0 = (rowbase + q0 + m0w + g) * Cn + hcol;
    size_t orow1 = orow0 + (size_t)8 * Cn;
#pragma unroll
    for (int nt = 0; nt < 8; nt++) {
        int c = nt * 8 + 2 * qd;
        float v0 = o[nt][0] * inv0, v1 = o[nt][1] * inv0;
        uint32_t hh = pk_f16x2(v0, v1);
        ((uint32_t*)atthi)[(orow0 + c) >> 1] = hh;
        ((uint32_t*)attlo)[(orow0 + c) >> 1] =
            pk_f16x2(v0 - f16low(hh), v1 - f16high(hh));
        v0 = o[nt][2] * inv1; v1 = o[nt][3] * inv1;
        hh = pk_f16x2(v0, v1);
        ((uint32_t*)atthi)[(orow1 + c) >> 1] = hh;
        ((uint32_t*)attlo)[(orow1 + c) >> 1] =
            pk_f16x2(v0 - f16low(hh), v1 - f16high(hh));
    }
}

// ---------------------------------------------------------------------------
extern "C" void kernel_launch(void* const* d_in, const int* in_sizes, int n_in,
                              void* d_out, int out_size)
{
    const float* x     = (const float*)d_in[0];
    const float* Wqkv  = (const float*)d_in[1];
    const float* bqkv  = (const float*)d_in[2];
    const float* Wproj = (const float*)d_in[3];
    const float* bproj = (const float*)d_in[4];
    float* out = (float*)d_out;

    __half *xhi, *xlo, *wq16, *wp16, *qkvh, *qkvl, *ahi, *alo;
    cudaGetSymbolAddress((void**)&xhi, g_xhi);
    cudaGetSymbolAddress((void**)&xlo, g_xlo);
    cudaGetSymbolAddress((void**)&wq16, g_wqkv16);
    cudaGetSymbolAddress((void**)&wp16, g_wproj16);
    cudaGetSymbolAddress((void**)&qkvh, g_qkvh);
    cudaGetSymbolAddress((void**)&qkvl, g_qkvl);
    cudaGetSymbolAddress((void**)&ahi, g_atthi);
    cudaGetSymbolAddress((void**)&alo, g_attlo);

    cudaFuncSetAttribute(gemm_f16x2<0>, cudaFuncAttributeMaxDynamicSharedMemorySize, GEMM_SMEM);
    cudaFuncSetAttribute(gemm_f16x2<1>, cudaFuncAttributeMaxDynamicSharedMemorySize, GEMM_SMEM);

    int nx = Mn * Cn / 4, nwq = Cn * 3 * Cn / 4, nwp = Cn * Cn / 4;
    pack_hilo16_kernel<<<(nx + 255) / 256, 256>>>((const float4*)x, (uint2*)xhi, (uint2*)xlo, nx);
    pack16_kernel<<<(nwq + 255) / 256, 256>>>((const float4*)Wqkv, (uint2*)wq16, nwq);
    pack16_kernel<<<(nwp + 255) / 256, 256>>>((const float4*)Wproj, (uint2*)wp16, nwp);

    // 1) QKV = X @ W_qkv + b  -> fp16 hi/lo
    gemm_f16x2<1><<<dim3(3 * Cn / 128, Mn / 128), 128, GEMM_SMEM>>>(
        (const uint4*)xhi, (const uint4*)xlo, (const uint4*)wq16,
        bqkv, nullptr, qkvh, qkvl, Mn, 3 * Cn, Cn);

    // 2) causal flash attention (fp16 2-term); emits fp16 hi/lo att
    attn_mma_kernel<<<dim3(Tn / 64, Bn * Hn), 128>>>(qkvh, qkvl, ahi, alo);

    // 3) out = att @ W_proj + b  (fp32 out)
    gemm_f16x2<0><<<dim3(Cn / 128, Mn / 128), 128, GEMM_SMEM>>>(
        (const uint4*)ahi, (const uint4*)alo, (const uint4*)wp16,
        bproj, out, nullptr, nullptr, Mn, Cn, Cn);
}

// round 16
// speedup vs baseline: 1.1973x; 1.1664x over previous
#include <cuda_runtime.h>
#include <cuda_bf16.h>
#include <cuda_fp16.h>
#include <cstdint>

#define Bn 4
#define Tn 2048
#define Cn 1024
#define Hn 16
#define Mn (Bn * Tn)

// ---------------- scratch (__device__ globals, no runtime alloc) ------------
__device__ __align__(16) __half g_xhi[(size_t)Mn * Cn];
__device__ __align__(16) __half g_xlo[(size_t)Mn * Cn];
__device__ __align__(16) __half g_wqkv16[(size_t)Cn * 3 * Cn];
__device__ __align__(16) __half g_wproj16[(size_t)Cn * Cn];
__device__ __align__(16) __half g_qkvh[(size_t)Mn * 3 * Cn];
__device__ __align__(16) __half g_qkvl[(size_t)Mn * 3 * Cn];
__device__ __align__(16) __half g_att16[(size_t)Mn * Cn];    // att single fp16

// ---------------- helpers ----------------------------------------------------
__device__ __forceinline__ uint32_t pk_f16x2(float lo, float hi) {
    __half2 h = __floats2half2_rn(lo, hi);
    return *(uint32_t*)&h;
}
__device__ __forceinline__ float f16low(uint32_t u)  { return __low2float(*(__half2*)&u); }
__device__ __forceinline__ float f16high(uint32_t u) { return __high2float(*(__half2*)&u); }

__device__ __forceinline__ void ldsm4(uint32_t& r0, uint32_t& r1, uint32_t& r2,
                                      uint32_t& r3, uint32_t a) {
    asm volatile("ldmatrix.sync.aligned.m8n8.x4.shared.b16 {%0,%1,%2,%3}, [%4];"
                 : "=r"(r0), "=r"(r1), "=r"(r2), "=r"(r3) : "r"(a));
}
__device__ __forceinline__ void ldsm4t(uint32_t& r0, uint32_t& r1, uint32_t& r2,
                                       uint32_t& r3, uint32_t a) {
    asm volatile("ldmatrix.sync.aligned.m8n8.x4.trans.shared.b16 {%0,%1,%2,%3}, [%4];"
                 : "=r"(r0), "=r"(r1), "=r"(r2), "=r"(r3) : "r"(a));
}
__device__ __forceinline__ void hmma16(float d[4], const uint32_t a[4], const uint32_t b[2]) {
    asm volatile(
        "mma.sync.aligned.m16n8k16.row.col.f32.f16.f16.f32 "
        "{%0,%1,%2,%3}, {%4,%5,%6,%7}, {%8,%9}, {%0,%1,%2,%3};"
        : "+f"(d[0]), "+f"(d[1]), "+f"(d[2]), "+f"(d[3])
        : "r"(a[0]), "r"(a[1]), "r"(a[2]), "r"(a[3]), "r"(b[0]), "r"(b[1]));
}
__device__ __forceinline__ void cpa16(uint32_t s, const void* g) {
    asm volatile("cp.async.cg.shared.global [%0], [%1], 16;" :: "r"(s), "l"(g) : "memory");
}

// ---------------- pack fp32 -> hi/lo fp16 (X, exact 2-term split) -------------
__global__ __launch_bounds__(256)
void pack_hilo16_kernel(const float4* __restrict__ in, uint2* __restrict__ ohi,
                        uint2* __restrict__ olo, int n4)
{
    int i = blockIdx.x * 256 + threadIdx.x;
    if (i >= n4) return;
    float4 v = in[i];
    uint32_t h0 = pk_f16x2(v.x, v.y);
    uint32_t h1 = pk_f16x2(v.z, v.w);
    ohi[i] = make_uint2(h0, h1);
    olo[i] = make_uint2(pk_f16x2(v.x - f16low(h0), v.y - f16high(h0)),
                        pk_f16x2(v.z - f16low(h1), v.w - f16high(h1)));
}

// ---------------- pack fp32 -> single fp16 (weights) ---------------------------
__global__ __launch_bounds__(256)
void pack16_kernel(const float4* __restrict__ in, uint2* __restrict__ o, int n4)
{
    int i = blockIdx.x * 256 + threadIdx.x;
    if (i >= n4) return;
    float4 v = in[i];
    o[i] = make_uint2(pk_f16x2(v.x, v.y), pk_f16x2(v.z, v.w));
}

// ---------------- fp16 HMMA GEMM, 4 warps x 64x64 warp tiles -------------------
// C[M,N] = (Ahi [+ Alo])[M,K] @ B16[K,N] + bias   (B single fp16)
// Round-13 proven 2-stage pipeline. TERMS = 1 or 2 A-terms.
// OUT_MODE 0: fp32 out. OUT_MODE 1: fp16 hi/lo split out.
#define ABUF 8192
#define BBUF 8704

template <int OUT_MODE, int TERMS>
__global__ __launch_bounds__(128, 2)
void gemm_f16(const uint4* __restrict__ Ahi, const uint4* __restrict__ Alo,
              const uint4* __restrict__ B16,
              const float* __restrict__ bias, float* __restrict__ Cm,
              __half* __restrict__ Chi, __half* __restrict__ Clo,
              int M, int N, int K)
{
    constexpr int STG = TERMS * ABUF + BBUF;
    extern __shared__ __align__(1024) char dsm[];
    const int tid  = threadIdx.x;
    const int lane = tid & 31;
    const int warp = tid >> 5;
    const int wm   = warp >> 1;
    const int wn   = warp & 1;
    const int row0 = blockIdx.y * 128;
    const int col0 = blockIdx.x * 128;
    const uint32_t sb0 = (uint32_t)__cvta_generic_to_shared(dsm);

    const int NT = K >> 5;
    const int Kv = K >> 3;
    const int Nv = N >> 3;

    const int ar = tid >> 2;
    const int ag = tid & 3;
    const int bkr = tid >> 4;
    const int bc  = tid & 15;

    const int L  = lane;
    const int fr = (L & 7) + ((L >> 3) & 1) * 8;
    const int fa = ((L & 7) & 6) << 1;
    const uint32_t aoff = (uint32_t)(((wm * 64 + fr) * 16 + ((4 * (L >> 4)) ^ fa)) * 4);
    const uint32_t boff = (uint32_t)(fr * 272 + (wn * 64 + (L >> 4) * 8) * 2);

    auto load_chunk = [&](int ck) {
        uint32_t sb = sb0 + (uint32_t)((ck & 1) * STG);
#pragma unroll
        for (int i = 0; i < 4; i++) {
            int m = ar + i * 32;
            int f = (m & 6) << 1;
            uint32_t so = (uint32_t)((m * 16 + ((4 * ag) ^ f)) * 4);
            size_t ga = (size_t)(row0 + m) * Kv + ck * 4 + ag;
            cpa16(sb + so, Ahi + ga);
            if (TERMS == 2) cpa16(sb + ABUF + so, Alo + ga);
        }
#pragma unroll
        for (int i = 0; i < 4; i++) {
            int kr = bkr + i * 8;
            uint32_t so = (uint32_t)(kr * 272 + bc * 16);
            size_t gb = (size_t)(ck * 32 + kr) * Nv + (col0 >> 3) + bc;
            cpa16(sb + TERMS * ABUF + so, B16 + gb);
        }
        asm volatile("cp.async.commit_group;" ::: "memory");
    };

    float acc[4][8][4];
#pragma unroll
    for (int mi = 0; mi < 4; mi++)
#pragma unroll
        for (int na = 0; na < 8; na++)
#pragma unroll
            for (int r = 0; r < 4; r++) acc[mi][na][r] = 0.0f;

    load_chunk(0);

    for (int kt = 0; kt < NT; kt++) {
        if (kt + 1 < NT) {
            load_chunk(kt + 1);
            asm volatile("cp.async.wait_group 1;" ::: "memory");
        } else {
            asm volatile("cp.async.wait_group 0;" ::: "memory");
        }
        __syncthreads();

        uint32_t sa  = sb0 + (uint32_t)((kt & 1) * STG);
        uint32_t sbB = sa + TERMS * ABUF;

#pragma unroll
        for (int ks = 0; ks < 2; ks++) {
            const uint32_t ax = (uint32_t)(ks * 32);
            uint32_t a_hi[4][4], a_lo[4][4];
#pragma unroll
            for (int mi = 0; mi < 4; mi++) {
                uint32_t ad = (sa + aoff + (uint32_t)(mi * 1024)) ^ ax;
                ldsm4(a_hi[mi][0], a_hi[mi][1], a_hi[mi][2], a_hi[mi][3], ad);
                if (TERMS == 2)
                    ldsm4(a_lo[mi][0], a_lo[mi][1], a_lo[mi][2], a_lo[mi][3], ad + ABUF);
            }
#pragma unroll
            for (int nh = 0; nh < 2; nh++) {
                uint32_t bd = sbB + boff + (uint32_t)(nh * 64 + ks * 4352);
                uint32_t bfr[4][2];
                ldsm4t(bfr[0][0], bfr[0][1], bfr[1][0], bfr[1][1], bd);
                ldsm4t(bfr[2][0], bfr[2][1], bfr[3][0], bfr[3][1], bd + 32);
#pragma unroll
                for (int mi = 0; mi < 4; mi++)
#pragma unroll
                    for (int ni = 0; ni < 4; ni++)
                        hmma16(acc[mi][nh * 4 + ni], a_hi[mi], bfr[ni]);
                if (TERMS == 2) {
#pragma unroll
                    for (int mi = 0; mi < 4; mi++)
#pragma unroll
                        for (int ni = 0; ni < 4; ni++)
                            hmma16(acc[mi][nh * 4 + ni], a_lo[mi], bfr[ni]);
                }
            }
        }
        __syncthreads();
    }

    // ---- epilogue ----
    const int g = lane >> 2, qd = lane & 3;
#pragma unroll
    for (int mi = 0; mi < 4; mi++) {
        int row = row0 + wm * 64 + mi * 16 + g;
#pragma unroll
        for (int na = 0; na < 8; na++) {
            int col = col0 + wn * 64 + na * 8 + 2 * qd;
            float2 bv = *(const float2*)&bias[col];
            float v0 = acc[mi][na][0] + bv.x, v1 = acc[mi][na][1] + bv.y;
            float v2 = acc[mi][na][2] + bv.x, v3 = acc[mi][na][3] + bv.y;
            if (OUT_MODE == 0) {
                *(float2*)&Cm[(size_t)row * N + col]       = make_float2(v0, v1);
                *(float2*)&Cm[(size_t)(row + 8) * N + col] = make_float2(v2, v3);
            } else {
                uint32_t hh = pk_f16x2(v0, v1);
                size_t i0 = ((size_t)row * N + col) >> 1;
                ((uint32_t*)Chi)[i0] = hh;
                ((uint32_t*)Clo)[i0] = pk_f16x2(v0 - f16low(hh), v1 - f16high(hh));
                hh = pk_f16x2(v2, v3);
                size_t i1 = ((size_t)(row + 8) * N + col) >> 1;
                ((uint32_t*)Chi)[i1] = hh;
                ((uint32_t*)Clo)[i1] = pk_f16x2(v2 - f16low(hh), v3 - f16high(hh));
            }
        }
    }
}

#define GEMM_SMEM_T2 (2 * (2 * ABUF + BBUF))   // 50176
#define GEMM_SMEM_T1 (2 * (ABUF + BBUF))       // 33792

// ---------------- fp16 flash attention (causal) -------------------------------
// Round-13 structure. S = (Qhi+Qlo)@Khi^T (2-term);  O = Phi@Vhi (1-term).
// Epilogue stores att as SINGLE fp16 (proj is 1-term).
__global__ __launch_bounds__(128)
void attn_mma_kernel(const __half* __restrict__ qh,
                     const __half* __restrict__ ql,
                     __half* __restrict__ att16)
{
    __shared__ __align__(16) __half sKh[64 * 72];
    __shared__ __align__(16) __half sVh[64 * 72];

    const int tid  = threadIdx.x;
    const int lane = tid & 31;
    const int warp = tid >> 5;
    const int qt   = (int)(gridDim.x - 1) - (int)blockIdx.x;  // heavy tiles first
    const int bh   = blockIdx.y;
    const int b    = bh >> 4, h = bh & 15;
    const int q0   = qt * 64;
    const int m0w  = warp * 16;
    const int g    = lane >> 2, qd = lane & 3;
    const size_t rowbase = (size_t)b * Tn;
    const int hcol = h * 64;

    const int fr = (lane & 7) + ((lane >> 3) & 1) * 8;
    const int hb = (lane >> 4) * 16;

    uint32_t sKh_b = (uint32_t)__cvta_generic_to_shared(sKh);
    uint32_t sVh_b = (uint32_t)__cvta_generic_to_shared(sVh);

    // ---- stage Q: hi -> sKh, lo -> sVh; fragments into registers ----
#pragma unroll
    for (int it = 0; it < 4; it++) {
        int idx = tid + it * 128;
        int r = idx >> 3, c = idx & 7;
        size_t grow = (rowbase + q0 + r) * (3 * Cn) + hcol;
        ((uint4*)sKh)[r * 9 + c] = *((const uint4*)(qh + grow) + c);
        ((uint4*)sVh)[r * 9 + c] = *((const uint4*)(ql + grow) + c);
    }
    __syncthreads();

    uint32_t qhi[4][4], qlo[4][4];
#pragma unroll
    for (int j = 0; j < 4; j++) {
        uint32_t ad = (uint32_t)((m0w + fr) * 144 + j * 32 + hb);
        ldsm4(qhi[j][0], qhi[j][1], qhi[j][2], qhi[j][3], sKh_b + ad);
        ldsm4(qlo[j][0], qlo[j][1], qlo[j][2], qlo[j][3], sVh_b + ad);
    }

    float o[8][4];
#pragma unroll
    for (int nt = 0; nt < 8; nt++)
#pragma unroll
        for (int r = 0; r < 4; r++) o[nt][r] = 0.0f;
    float m0r = -1e30f, m1r = -1e30f, l0 = 0.0f, l1 = 0.0f;

    const float scale = 0.125f;
    const int rl0 = m0w + g, rl1 = rl0 + 8;

    for (int t = 0; t <= qt; t++) {
        const int kv0 = t * 64;
        __syncthreads();
#pragma unroll
        for (int it = 0; it < 4; it++) {
            int idx = tid + it * 128;
            int r = idx >> 3, c = idx & 7;
            size_t grow = (rowbase + kv0 + r) * (3 * Cn) + hcol;
            ((uint4*)sKh)[r * 9 + c] = *((const uint4*)(qh + grow + Cn) + c);
            ((uint4*)sVh)[r * 9 + c] = *((const uint4*)(qh + grow + 2 * Cn) + c);
        }
        __syncthreads();

        // ---- S = Q K^T (2-term fp16) ----
        float s[8][4];
#pragma unroll
        for (int nt = 0; nt < 8; nt++)
#pragma unroll
            for (int r = 0; r < 4; r++) s[nt][r] = 0.0f;

#pragma unroll
        for (int p = 0; p < 4; p++) {
#pragma unroll
            for (int j = 0; j < 4; j++) {
                uint32_t kh0, kh1, kh2, kh3;
                uint32_t ad = (uint32_t)((p * 16 + fr) * 144 + j * 32 + hb);
                ldsm4(kh0, kh1, kh2, kh3, sKh_b + ad);
                uint32_t b0h[2] = {kh0, kh2}, b1h[2] = {kh1, kh3};
                hmma16(s[2 * p],     qhi[j], b0h);
                hmma16(s[2 * p],     qlo[j], b0h);
                hmma16(s[2 * p + 1], qhi[j], b1h);
                hmma16(s[2 * p + 1], qlo[j], b1h);
            }
        }

        // ---- scale + causal mask (diagonal tile only) ----
#pragma unroll
        for (int nt = 0; nt < 8; nt++) {
            s[nt][0] *= scale; s[nt][1] *= scale;
            s[nt][2] *= scale; s[nt][3] *= scale;
        }
        if (t == qt) {
#pragma unroll
            for (int nt = 0; nt < 8; nt++) {
                int c0 = nt * 8 + 2 * qd;
                if (c0     > rl0) s[nt][0] = -1e30f;
                if (c0 + 1 > rl0) s[nt][1] = -1e30f;
                if (c0     > rl1) s[nt][2] = -1e30f;
                if (c0 + 1 > rl1) s[nt][3] = -1e30f;
            }
        }

        // ---- online softmax (rows g and g+8) ----
        float mx0 = -1e30f, mx1 = -1e30f;
#pragma unroll
        for (int nt = 0; nt < 8; nt++) {
            mx0 = fmaxf(mx0, fmaxf(s[nt][0], s[nt][1]));
            mx1 = fmaxf(mx1, fmaxf(s[nt][2], s[nt][3]));
        }
        mx0 = fmaxf(mx0, __shfl_xor_sync(0xffffffffu, mx0, 1));
        mx0 = fmaxf(mx0, __shfl_xor_sync(0xffffffffu, mx0, 2));
        mx1 = fmaxf(mx1, __shfl_xor_sync(0xffffffffu, mx1, 1));
        mx1 = fmaxf(mx1, __shfl_xor_sync(0xffffffffu, mx1, 2));
        float mn0 = fmaxf(m0r, mx0), mn1 = fmaxf(m1r, mx1);
        float cf0 = __expf(m0r - mn0), cf1 = __expf(m1r - mn1);
        m0r = mn0; m1r = mn1;
        float sum0 = 0.0f, sum1 = 0.0f;
#pragma unroll
        for (int nt = 0; nt < 8; nt++) {
            s[nt][0] = __expf(s[nt][0] - mn0); sum0 += s[nt][0];
            s[nt][1] = __expf(s[nt][1] - mn0); sum0 += s[nt][1];
            s[nt][2] = __expf(s[nt][2] - mn1); sum1 += s[nt][2];
            s[nt][3] = __expf(s[nt][3] - mn1); sum1 += s[nt][3];
        }
        sum0 += __shfl_xor_sync(0xffffffffu, sum0, 1);
        sum0 += __shfl_xor_sync(0xffffffffu, sum0, 2);
        sum1 += __shfl_xor_sync(0xffffffffu, sum1, 1);
        sum1 += __shfl_xor_sync(0xffffffffu, sum1, 2);
        l0 = l0 * cf0 + sum0;
        l1 = l1 * cf1 + sum1;
#pragma unroll
        for (int nt = 0; nt < 8; nt++) {
            o[nt][0] *= cf0; o[nt][1] *= cf0;
            o[nt][2] *= cf1; o[nt][3] *= cf1;
        }

        // ---- O += P V (1-term fp16: P hi only) ----
#pragma unroll
        for (int j = 0; j < 4; j++) {
            uint32_t phi[4];
            phi[0] = pk_f16x2(s[2 * j][0],     s[2 * j][1]);
            phi[1] = pk_f16x2(s[2 * j][2],     s[2 * j][3]);
            phi[2] = pk_f16x2(s[2 * j + 1][0], s[2 * j + 1][1]);
            phi[3] = pk_f16x2(s[2 * j + 1][2], s[2 * j + 1][3]);

#pragma unroll
            for (int p = 0; p < 4; p++) {
                uint32_t v0, v1, v2, v3;
                uint32_t ad = (uint32_t)((j * 16 + fr) * 144 + p * 32 + hb);
                ldsm4t(v0, v1, v2, v3, sVh_b + ad);
                uint32_t bh0[2] = {v0, v1}, bh1[2] = {v2, v3};
                hmma16(o[2 * p],     phi, bh0);
                hmma16(o[2 * p + 1], phi, bh1);
            }
        }
    }

    // ---- epilogue: normalize, store single fp16 ----
    float inv0 = 1.0f / l0, inv1 = 1.0f / l1;
    size_t orow0 = (rowbase + q0 + m0w + g) * Cn + hcol;
    size_t orow1 = orow0 + (size_t)8 * Cn;
#pragma unroll
    for (int nt = 0; nt < 8; nt++) {
        int c = nt * 8 + 2 * qd;
        ((uint32_t*)att16)[(orow0 + c) >> 1] =
            pk_f16x2(o[nt][0] * inv0, o[nt][1] * inv0);
        ((uint32_t*)att16)[(orow1 + c) >> 1] =
            pk_f16x2(o[nt][2] * inv1, o[nt][3] * inv1);
    }
}

// ---------------------------------------------------------------------------
extern "C" void kernel_launch(void* const* d_in, const int* in_sizes, int n_in,
                              void* d_out, int out_size)
{
    const float* x     = (const float*)d_in[0];
    const float* Wqkv  = (const float*)d_in[1];
    const float* bqkv  = (const float*)d_in[2];
    const float* Wproj = (const float*)d_in[3];
    const float* bproj = (const float*)d_in[4];
    float* out = (float*)d_out;

    __half *xhi, *xlo, *wq16, *wp16, *qkvh, *qkvl, *att16;
    cudaGetSymbolAddress((void**)&xhi, g_xhi);
    cudaGetSymbolAddress((void**)&xlo, g_xlo);
    cudaGetSymbolAddress((void**)&wq16, g_wqkv16);
    cudaGetSymbolAddress((void**)&wp16, g_wproj16);
    cudaGetSymbolAddress((void**)&qkvh, g_qkvh);
    cudaGetSymbolAddress((void**)&qkvl, g_qkvl);
    cudaGetSymbolAddress((void**)&att16, g_att16);

    cudaFuncSetAttribute((const void*)gemm_f16<1, 2>,
                         cudaFuncAttributeMaxDynamicSharedMemorySize, GEMM_SMEM_T2);
    cudaFuncSetAttribute((const void*)gemm_f16<0, 1>,
                         cudaFuncAttributeMaxDynamicSharedMemorySize, GEMM_SMEM_T1);

    int nx = Mn * Cn / 4, nwq = Cn * 3 * Cn / 4, nwp = Cn * Cn / 4;
    pack_hilo16_kernel<<<(nx + 255) / 256, 256>>>((const float4*)x, (uint2*)xhi, (uint2*)xlo, nx);
    pack16_kernel<<<(nwq + 255) / 256, 256>>>((const float4*)Wqkv, (uint2*)wq16, nwq);
    pack16_kernel<<<(nwp + 255) / 256, 256>>>((const float4*)Wproj, (uint2*)wp16, nwp);

    // 1) QKV = X @ W_qkv + b  -> fp16 hi/lo  (2-term A)
    gemm_f16<1, 2><<<dim3(3 * Cn / 128, Mn / 128), 128, GEMM_SMEM_T2>>>(
        (const uint4*)xhi, (const uint4*)xlo, (const uint4*)wq16,
        bqkv, nullptr, qkvh, qkvl, Mn, 3 * Cn, Cn);

    // 2) causal flash attention (S 2-term, PV 1-term); emits single fp16 att
    attn_mma_kernel<<<dim3(Tn / 64, Bn * Hn), 128>>>(qkvh, qkvl, att16);

    // 3) out = att @ W_proj + b  (1-term A, fp32 out)
    gemm_f16<0, 1><<<dim3(Cn / 128, Mn / 128), 128, GEMM_SMEM_T1>>>(
        (const uint4*)att16, nullptr, (const uint4*)wp16,
        bproj, out, nullptr, nullptr, Mn, Cn, Cn);
}

// round 17
// speedup vs baseline: 1.7070x; 1.4257x over previous
#include <cuda_runtime.h>
#include <cuda_bf16.h>
#include <cuda_fp16.h>
#include <cstdint>

#define Bn 4
#define Tn 2048
#define Cn 1024
#define Hn 16
#define Mn (Bn * Tn)

// ---------------- scratch (__device__ globals, no runtime alloc) ------------
__device__ __align__(16) __half g_x16[(size_t)Mn * Cn];        // X fp16
__device__ __align__(16) __half g_wqkv16[(size_t)Cn * 3 * Cn]; // W_qkv fp16
__device__ __align__(16) __half g_wproj16[(size_t)Cn * Cn];    // W_proj fp16
__device__ __align__(16) __half g_qkv16[(size_t)Mn * 3 * Cn];  // qkv fp16
__device__ __align__(16) __half g_att16[(size_t)Mn * Cn];      // att fp16

// ---------------- helpers ----------------------------------------------------
__device__ __forceinline__ uint32_t pk_f16x2(float lo, float hi) {
    __half2 h = __floats2half2_rn(lo, hi);
    return *(uint32_t*)&h;
}

__device__ __forceinline__ void ldsm4(uint32_t& r0, uint32_t& r1, uint32_t& r2,
                                      uint32_t& r3, uint32_t a) {
    asm volatile("ldmatrix.sync.aligned.m8n8.x4.shared.b16 {%0,%1,%2,%3}, [%4];"
                 : "=r"(r0), "=r"(r1), "=r"(r2), "=r"(r3) : "r"(a));
}
__device__ __forceinline__ void ldsm4t(uint32_t& r0, uint32_t& r1, uint32_t& r2,
                                       uint32_t& r3, uint32_t a) {
    asm volatile("ldmatrix.sync.aligned.m8n8.x4.trans.shared.b16 {%0,%1,%2,%3}, [%4];"
                 : "=r"(r0), "=r"(r1), "=r"(r2), "=r"(r3) : "r"(a));
}
__device__ __forceinline__ void hmma16(float d[4], const uint32_t a[4], const uint32_t b[2]) {
    asm volatile(
        "mma.sync.aligned.m16n8k16.row.col.f32.f16.f16.f32 "
        "{%0,%1,%2,%3}, {%4,%5,%6,%7}, {%8,%9}, {%0,%1,%2,%3};"
        : "+f"(d[0]), "+f"(d[1]), "+f"(d[2]), "+f"(d[3])
        : "r"(a[0]), "r"(a[1]), "r"(a[2]), "r"(a[3]), "r"(b[0]), "r"(b[1]));
}
__device__ __forceinline__ void cpa16(uint32_t s, const void* g) {
    asm volatile("cp.async.cg.shared.global [%0], [%1], 16;" :: "r"(s), "l"(g) : "memory");
}

// ---------------- pack fp32 -> single fp16 -------------------------------------
__global__ __launch_bounds__(256)
void pack16_kernel(const float4* __restrict__ in, uint2* __restrict__ o, int n4)
{
    int i = blockIdx.x * 256 + threadIdx.x;
    if (i >= n4) return;
    float4 v = in[i];
    o[i] = make_uint2(pk_f16x2(v.x, v.y), pk_f16x2(v.z, v.w));
}

// ---------------- fp16 1-term HMMA GEMM, 4 warps x 64x64 warp tiles ------------
// C[M,N] = A16[M,K] @ B16[K,N] + bias   (both single fp16)
// Round-13 proven 2-stage pipeline shape.
// OUT_MODE 0: fp32 out. OUT_MODE 1: fp16 out.
#define ABUF 8192
#define BBUF 8704
#define STG  (ABUF + BBUF)               // 16896
#define GEMM_SMEM (2 * STG)              // 33792

template <int OUT_MODE>
__global__ __launch_bounds__(128, 2)
void gemm_f16(const uint4* __restrict__ A16, const uint4* __restrict__ B16,
              const float* __restrict__ bias, float* __restrict__ Cm,
              __half* __restrict__ C16, int M, int N, int K)
{
    extern __shared__ __align__(1024) char dsm[];
    const int tid  = threadIdx.x;
    const int lane = tid & 31;
    const int warp = tid >> 5;
    const int wm   = warp >> 1;
    const int wn   = warp & 1;
    const int row0 = blockIdx.y * 128;
    const int col0 = blockIdx.x * 128;
    const uint32_t sb0 = (uint32_t)__cvta_generic_to_shared(dsm);

    const int NT = K >> 5;
    const int Kv = K >> 3;
    const int Nv = N >> 3;

    const int ar = tid >> 2;
    const int ag = tid & 3;
    const int bkr = tid >> 4;
    const int bc  = tid & 15;

    const int L  = lane;
    const int fr = (L & 7) + ((L >> 3) & 1) * 8;
    const int fa = ((L & 7) & 6) << 1;
    const uint32_t aoff = (uint32_t)(((wm * 64 + fr) * 16 + ((4 * (L >> 4)) ^ fa)) * 4);
    const uint32_t boff = (uint32_t)(fr * 272 + (wn * 64 + (L >> 4) * 8) * 2);

    auto load_chunk = [&](int ck) {
        uint32_t sb = sb0 + (uint32_t)((ck & 1) * STG);
#pragma unroll
        for (int i = 0; i < 4; i++) {
            int m = ar + i * 32;
            int f = (m & 6) << 1;
            uint32_t so = (uint32_t)((m * 16 + ((4 * ag) ^ f)) * 4);
            size_t ga = (size_t)(row0 + m) * Kv + ck * 4 + ag;
            cpa16(sb + so, A16 + ga);
        }
#pragma unroll
        for (int i = 0; i < 4; i++) {
            int kr = bkr + i * 8;
            uint32_t so = (uint32_t)(kr * 272 + bc * 16);
            size_t gb = (size_t)(ck * 32 + kr) * Nv + (col0 >> 3) + bc;
            cpa16(sb + ABUF + so, B16 + gb);
        }
        asm volatile("cp.async.commit_group;" ::: "memory");
    };

    float acc[4][8][4];
#pragma unroll
    for (int mi = 0; mi < 4; mi++)
#pragma unroll
        for (int na = 0; na < 8; na++)
#pragma unroll
            for (int r = 0; r < 4; r++) acc[mi][na][r] = 0.0f;

    load_chunk(0);

    for (int kt = 0; kt < NT; kt++) {
        if (kt + 1 < NT) {
            load_chunk(kt + 1);
            asm volatile("cp.async.wait_group 1;" ::: "memory");
        } else {
            asm volatile("cp.async.wait_group 0;" ::: "memory");
        }
        __syncthreads();

        uint32_t sa  = sb0 + (uint32_t)((kt & 1) * STG);
        uint32_t sbB = sa + ABUF;

#pragma unroll
        for (int ks = 0; ks < 2; ks++) {
            const uint32_t ax = (uint32_t)(ks * 32);
            uint32_t a16[4][4];
#pragma unroll
            for (int mi = 0; mi < 4; mi++) {
                uint32_t ad = (sa + aoff + (uint32_t)(mi * 1024)) ^ ax;
                ldsm4(a16[mi][0], a16[mi][1], a16[mi][2], a16[mi][3], ad);
            }
#pragma unroll
            for (int nh = 0; nh < 2; nh++) {
                uint32_t bd = sbB + boff + (uint32_t)(nh * 64 + ks * 4352);
                uint32_t bfr[4][2];
                ldsm4t(bfr[0][0], bfr[0][1], bfr[1][0], bfr[1][1], bd);
                ldsm4t(bfr[2][0], bfr[2][1], bfr[3][0], bfr[3][1], bd + 32);
#pragma unroll
                for (int mi = 0; mi < 4; mi++)
#pragma unroll
                    for (int ni = 0; ni < 4; ni++)
                        hmma16(acc[mi][nh * 4 + ni], a16[mi], bfr[ni]);
            }
        }
        __syncthreads();
    }

    // ---- epilogue ----
    const int g = lane >> 2, qd = lane & 3;
#pragma unroll
    for (int mi = 0; mi < 4; mi++) {
        int row = row0 + wm * 64 + mi * 16 + g;
#pragma unroll
        for (int na = 0; na < 8; na++) {
            int col = col0 + wn * 64 + na * 8 + 2 * qd;
            float2 bv = *(const float2*)&bias[col];
            float v0 = acc[mi][na][0] + bv.x, v1 = acc[mi][na][1] + bv.y;
            float v2 = acc[mi][na][2] + bv.x, v3 = acc[mi][na][3] + bv.y;
            if (OUT_MODE == 0) {
                *(float2*)&Cm[(size_t)row * N + col]       = make_float2(v0, v1);
                *(float2*)&Cm[(size_t)(row + 8) * N + col] = make_float2(v2, v3);
            } else {
                ((uint32_t*)C16)[((size_t)row * N + col) >> 1]       = pk_f16x2(v0, v1);
                ((uint32_t*)C16)[((size_t)(row + 8) * N + col) >> 1] = pk_f16x2(v2, v3);
            }
        }
    }
}

// ---------------- fp16 1-term flash attention (causal) -------------------------
// 64 q-rows, 4 warps (round-13 structure). S = Q@K^T, O = P@V, all single fp16.
__global__ __launch_bounds__(128)
void attn_mma_kernel(const __half* __restrict__ qkv, __half* __restrict__ att16)
{
    __shared__ __align__(16) __half sKh[64 * 72];
    __shared__ __align__(16) __half sVh[64 * 72];

    const int tid  = threadIdx.x;
    const int lane = tid & 31;
    const int warp = tid >> 5;
    const int qt   = (int)(gridDim.x - 1) - (int)blockIdx.x;  // heavy tiles first
    const int bh   = blockIdx.y;
    const int b    = bh >> 4, h = bh & 15;
    const int q0   = qt * 64;
    const int m0w  = warp * 16;
    const int g    = lane >> 2, qd = lane & 3;
    const size_t rowbase = (size_t)b * Tn;
    const int hcol = h * 64;

    const int fr = (lane & 7) + ((lane >> 3) & 1) * 8;
    const int hb = (lane >> 4) * 16;

    uint32_t sKh_b = (uint32_t)__cvta_generic_to_shared(sKh);
    uint32_t sVh_b = (uint32_t)__cvta_generic_to_shared(sVh);

    // ---- stage Q into sKh; fragments into registers ----
#pragma unroll
    for (int it = 0; it < 4; it++) {
        int idx = tid + it * 128;
        int r = idx >> 3, c = idx & 7;
        size_t grow = (rowbase + q0 + r) * (3 * Cn) + hcol;
        ((uint4*)sKh)[r * 9 + c] = *((const uint4*)(qkv + grow) + c);
    }
    __syncthreads();

    uint32_t qfr[4][4];
#pragma unroll
    for (int j = 0; j < 4; j++) {
        uint32_t ad = (uint32_t)((m0w + fr) * 144 + j * 32 + hb);
        ldsm4(qfr[j][0], qfr[j][1], qfr[j][2], qfr[j][3], sKh_b + ad);
    }

    float o[8][4];
#pragma unroll
    for (int nt = 0; nt < 8; nt++)
#pragma unroll
        for (int r = 0; r < 4; r++) o[nt][r] = 0.0f;
    float m0r = -1e30f, m1r = -1e30f, l0 = 0.0f, l1 = 0.0f;

    const float scale = 0.125f;
    const int rl0 = m0w + g, rl1 = rl0 + 8;

    for (int t = 0; t <= qt; t++) {
        const int kv0 = t * 64;
        __syncthreads();
#pragma unroll
        for (int it = 0; it < 4; it++) {
            int idx = tid + it * 128;
            int r = idx >> 3, c = idx & 7;
            size_t grow = (rowbase + kv0 + r) * (3 * Cn) + hcol;
            ((uint4*)sKh)[r * 9 + c] = *((const uint4*)(qkv + grow + Cn) + c);
            ((uint4*)sVh)[r * 9 + c] = *((const uint4*)(qkv + grow + 2 * Cn) + c);
        }
        __syncthreads();

        // ---- S = Q K^T (1-term fp16) ----
        float s[8][4];
#pragma unroll
        for (int nt = 0; nt < 8; nt++)
#pragma unroll
            for (int r = 0; r < 4; r++) s[nt][r] = 0.0f;

#pragma unroll
        for (int p = 0; p < 4; p++) {
#pragma unroll
            for (int j = 0; j < 4; j++) {
                uint32_t kh0, kh1, kh2, kh3;
                uint32_t ad = (uint32_t)((p * 16 + fr) * 144 + j * 32 + hb);
                ldsm4(kh0, kh1, kh2, kh3, sKh_b + ad);
                uint32_t b0h[2] = {kh0, kh2}, b1h[2] = {kh1, kh3};
                hmma16(s[2 * p],     qfr[j], b0h);
                hmma16(s[2 * p + 1], qfr[j], b1h);
            }
        }

        // ---- scale + causal mask (diagonal tile only) ----
#pragma unroll
        for (int nt = 0; nt < 8; nt++) {
            s[nt][0] *= scale; s[nt][1] *= scale;
            s[nt][2] *= scale; s[nt][3] *= scale;
        }
        if (t == qt) {
#pragma unroll
            for (int nt = 0; nt < 8; nt++) {
                int c0 = nt * 8 + 2 * qd;
                if (c0     > rl0) s[nt][0] = -1e30f;
                if (c0 + 1 > rl0) s[nt][1] = -1e30f;
                if (c0     > rl1) s[nt][2] = -1e30f;
                if (c0 + 1 > rl1) s[nt][3] = -1e30f;
            }
        }

        // ---- online softmax (rows g and g+8) ----
        float mx0 = -1e30f, mx1 = -1e30f;
#pragma unroll
        for (int nt = 0; nt < 8; nt++) {
            mx0 = fmaxf(mx0, fmaxf(s[nt][0], s[nt][1]));
            mx1 = fmaxf(mx1, fmaxf(s[nt][2], s[nt][3]));
        }
        mx0 = fmaxf(mx0, __shfl_xor_sync(0xffffffffu, mx0, 1));
        mx0 = fmaxf(mx0, __shfl_xor_sync(0xffffffffu, mx0, 2));
        mx1 = fmaxf(mx1, __shfl_xor_sync(0xffffffffu, mx1, 1));
        mx1 = fmaxf(mx1, __shfl_xor_sync(0xffffffffu, mx1, 2));
        float mn0 = fmaxf(m0r, mx0), mn1 = fmaxf(m1r, mx1);
        float cf0 = __expf(m0r - mn0), cf1 = __expf(m1r - mn1);
        m0r = mn0; m1r = mn1;
        float sum0 = 0.0f, sum1 = 0.0f;
#pragma unroll
        for (int nt = 0; nt < 8; nt++) {
            s[nt][0] = __expf(s[nt][0] - mn0); sum0 += s[nt][0];
            s[nt][1] = __expf(s[nt][1] - mn0); sum0 += s[nt][1];
            s[nt][2] = __expf(s[nt][2] - mn1); sum1 += s[nt][2];
            s[nt][3] = __expf(s[nt][3] - mn1); sum1 += s[nt][3];
        }
        sum0 += __shfl_xor_sync(0xffffffffu, sum0, 1);
        sum0 += __shfl_xor_sync(0xffffffffu, sum0, 2);
        sum1 += __shfl_xor_sync(0xffffffffu, sum1, 1);
        sum1 += __shfl_xor_sync(0xffffffffu, sum1, 2);
        l0 = l0 * cf0 + sum0;
        l1 = l1 * cf1 + sum1;
#pragma unroll
        for (int nt = 0; nt < 8; nt++) {
            o[nt][0] *= cf0; o[nt][1] *= cf0;
            o[nt][2] *= cf1; o[nt][3] *= cf1;
        }

        // ---- O += P V (1-term fp16) ----
#pragma unroll
        for (int j = 0; j < 4; j++) {
            uint32_t pfr[4];
            pfr[0] = pk_f16x2(s[2 * j][0],     s[2 * j][1]);
            pfr[1] = pk_f16x2(s[2 * j][2],     s[2 * j][3]);
            pfr[2] = pk_f16x2(s[2 * j + 1][0], s[2 * j + 1][1]);
            pfr[3] = pk_f16x2(s[2 * j + 1][2], s[2 * j + 1][3]);

#pragma unroll
            for (int p = 0; p < 4; p++) {
                uint32_t v0, v1, v2, v3;
                uint32_t ad = (uint32_t)((j * 16 + fr) * 144 + p * 32 + hb);
                ldsm4t(v0, v1, v2, v3, sVh_b + ad);
                uint32_t bh0[2] = {v0, v1}, bh1[2] = {v2, v3};
                hmma16(o[2 * p],     pfr, bh0);
                hmma16(o[2 * p + 1], pfr, bh1);
            }
        }
    }

    // ---- epilogue: normalize, store single fp16 ----
    float inv0 = 1.0f / l0, inv1 = 1.0f / l1;
    size_t orow0 = (rowbase + q0 + m0w + g) * Cn + hcol;
    size_t orow1 = orow0 + (size_t)8 * Cn;
#pragma unroll
    for (int nt = 0; nt < 8; nt++) {
        int c = nt * 8 + 2 * qd;
        ((uint32_t*)att16)[(orow0 + c) >> 1] =
            pk_f16x2(o[nt][0] * inv0, o[nt][1] * inv0);
        ((uint32_t*)att16)[(orow1 + c) >> 1] =
            pk_f16x2(o[nt][2] * inv1, o[nt][3] * inv1);
    }
}

// ---------------------------------------------------------------------------
extern "C" void kernel_launch(void* const* d_in, const int* in_sizes, int n_in,
                              void* d_out, int out_size)
{
    const float* x     = (const float*)d_in[0];
    const float* Wqkv  = (const float*)d_in[1];
    const float* bqkv  = (const float*)d_in[2];
    const float* Wproj = (const float*)d_in[3];
    const float* bproj = (const float*)d_in[4];
    float* out = (float*)d_out;

    __half *x16, *wq16, *wp16, *qkv16, *att16;
    cudaGetSymbolAddress((void**)&x16, g_x16);
    cudaGetSymbolAddress((void**)&wq16, g_wqkv16);
    cudaGetSymbolAddress((void**)&wp16, g_wproj16);
    cudaGetSymbolAddress((void**)&qkv16, g_qkv16);
    cudaGetSymbolAddress((void**)&att16, g_att16);

    cudaFuncSetAttribute((const void*)gemm_f16<1>,
                         cudaFuncAttributeMaxDynamicSharedMemorySize, GEMM_SMEM);
    cudaFuncSetAttribute((const void*)gemm_f16<0>,
                         cudaFuncAttributeMaxDynamicSharedMemorySize, GEMM_SMEM);

    int nx = Mn * Cn / 4, nwq = Cn * 3 * Cn / 4, nwp = Cn * Cn / 4;
    pack16_kernel<<<(nx + 255) / 256, 256>>>((const float4*)x, (uint2*)x16, nx);
    pack16_kernel<<<(nwq + 255) / 256, 256>>>((const float4*)Wqkv, (uint2*)wq16, nwq);
    pack16_kernel<<<(nwp + 255) / 256, 256>>>((const float4*)Wproj, (uint2*)wp16, nwp);

    // 1) QKV = X @ W_qkv + b  -> fp16
    gemm_f16<1><<<dim3(3 * Cn / 128, Mn / 128), 128, GEMM_SMEM>>>(
        (const uint4*)x16, (const uint4*)wq16, bqkv, nullptr, qkv16,
        Mn, 3 * Cn, Cn);

    // 2) causal flash attention (all fp16); emits fp16 att
    attn_mma_kernel<<<dim3(Tn / 64, Bn * Hn), 128>>>(qkv16, att16);

    // 3) out = att @ W_proj + b  (fp32 out)
    gemm_f16<0><<<dim3(Cn / 128, Mn / 128), 128, GEMM_SMEM>>>(
        (const uint4*)att16, (const uint4*)wp16, bproj, out, nullptr,
        Mn, Cn, Cn);
}